// round 12
// baseline (speedup 1.0000x reference)
#include <cuda_runtime.h>
#include <cuda.h>
#include <cuda_bf16.h>
#include <math.h>
#include <stdint.h>

#define IN_F   4096
#define OUT_F  1024
#define BSZ    8192
#define COLS   9216
#define COLS4  2304
#define GROUPS 2048
#define ROUNDS 12

#define KCH    128            // int8 elems per chunk = 128 bytes
#define CHPS   32             // chunks per segment
#define NSEG   9
#define NCH    (NSEG * CHPS)  // 288
#define NSTG   4
#define A_BYTES (128 * 128)
#define B_BYTES (64 * 128)
#define ST_BYTES (A_BYTES + B_BYTES)
#define DSMEM (1024 + NSTG * ST_BYTES)

// ---------------- device scratch ----------------
__device__ __align__(128) float g_a[(size_t)IN_F * COLS];
__device__ __align__(128) float g_b[(size_t)IN_F * COLS];
__device__ __align__(128) float g_wmats[ROUNDS * GROUPS * 4];
__device__ unsigned g_mm[4];
__device__ unsigned g_amax[4];       // maxabs: x, nx, wn, wp
__device__ float    g_qp[4];         // sx, zx, sw, zw
__device__ float    g_cs[16];        // 4 tensors x {s1, is1, s2, is2}
__device__ float    g_segscale[12];
__device__ int      g_sums[COLS];    // Sx[0..8191], Sw at +BSZ

__device__ __align__(128) int8_t g_qx8 [(size_t)BSZ   * IN_F];
__device__ __align__(128) int8_t g_q1x [(size_t)BSZ   * IN_F];
__device__ __align__(128) int8_t g_q2x [(size_t)BSZ   * IN_F];
__device__ __align__(128) int8_t g_q1nx[(size_t)BSZ   * IN_F];
__device__ __align__(128) int8_t g_q2nx[(size_t)BSZ   * IN_F];
__device__ __align__(128) int8_t g_qw8 [(size_t)OUT_F * IN_F];
__device__ __align__(128) int8_t g_q1wn[(size_t)OUT_F * IN_F];
__device__ __align__(128) int8_t g_q2wn[(size_t)OUT_F * IN_F];
__device__ __align__(128) int8_t g_q1wp[(size_t)OUT_F * IN_F];
__device__ __align__(128) int8_t g_q2wp[(size_t)OUT_F * IN_F];

struct TmapPack { CUtensorMap a[5]; CUtensorMap b[5]; };

// ---------------- helpers ----------------
__device__ __forceinline__ unsigned enc_f(float f) {
    unsigned u = __float_as_uint(f);
    return (u & 0x80000000u) ? ~u : (u | 0x80000000u);
}
__device__ __forceinline__ float dec_f(unsigned k) {
    return __uint_as_float((k & 0x80000000u) ? (k ^ 0x80000000u) : ~k);
}
__device__ __forceinline__ uint32_t smem_u32(const void* p) {
    uint32_t a;
    asm("{ .reg .u64 t; cvta.to.shared.u64 t, %1; cvt.u32.u64 %0, t; }" : "=r"(a) : "l"(p));
    return a;
}

#define MBAR_INIT(addr, cnt) \
    asm volatile("mbarrier.init.shared.b64 [%0], %1;" :: "r"(addr), "r"(cnt) : "memory")
#define MBAR_EXPECT_TX(addr, bytes) \
    asm volatile("mbarrier.arrive.expect_tx.shared.b64 _, [%0], %1;" :: "r"(addr), "r"(bytes) : "memory")
#define MBAR_WAIT(addr, par) do {                                              \
    asm volatile(                                                              \
        "{\n\t.reg .pred P;\n\t"                                               \
        "WL_%=:\n\t"                                                           \
        "mbarrier.try_wait.parity.acquire.cta.shared::cta.b64 P, [%0], %1, 0x989680;\n\t" \
        "@P bra.uni WD_%=;\n\t"                                                \
        "bra.uni WL_%=;\n\t"                                                   \
        "WD_%=:\n\t}"                                                          \
        :: "r"(addr), "r"(par) : "memory");                                    \
} while (0)

#define TMA_2D(smem, map, cx, cy, mbar) \
    asm volatile("cp.async.bulk.tensor.2d.shared::cta.global.tile.mbarrier::complete_tx::bytes " \
                 "[%0], [%1, {%2, %3}], [%4];" \
                 :: "r"(smem), "l"(map), "r"(cx), "r"(cy), "r"(mbar) : "memory")

// ---------------- inv(m)^T via LU w/ partial pivoting ----------------
__global__ void make_wmats_kernel(const float* __restrict__ mats) {
    int idx = blockIdx.x * blockDim.x + threadIdx.x;
    if (idx >= ROUNDS * GROUPS) return;
    const float* m = mats + (size_t)idx * 4;
    float a = m[0], b = m[1], c = m[2], d = m[3];
    float i00, i01, i10, i11;
    if (fabsf(c) > fabsf(a)) {
        float l   = __fdiv_rn(a, c);
        float u22 = __fmaf_rn(-l, d, b);
        float x2c1 = __fdiv_rn(1.0f, u22);
        float x1c1 = __fdiv_rn(__fmul_rn(-d, x2c1), c);
        float x2c2 = __fdiv_rn(-l, u22);
        float x1c2 = __fdiv_rn(__fmaf_rn(-d, x2c2, 1.0f), c);
        i00 = x1c1; i01 = x1c2; i10 = x2c1; i11 = x2c2;
    } else {
        float l   = __fdiv_rn(c, a);
        float u22 = __fmaf_rn(-l, b, d);
        float x2c1 = __fdiv_rn(-l, u22);
        float x1c1 = __fdiv_rn(__fmaf_rn(-b, x2c1, 1.0f), a);
        float x2c2 = __fdiv_rn(1.0f, u22);
        float x1c2 = __fdiv_rn(__fmul_rn(-b, x2c2), a);
        i00 = x1c1; i01 = x1c2; i10 = x2c1; i11 = x2c2;
    }
    float* o = g_wmats + (size_t)idx * 4;
    o[0] = i00; o[1] = i10; o[2] = i01; o[3] = i11;
}

// ---------------- init ----------------
__global__ void reset_kernel() {
    int t = blockIdx.x * blockDim.x + threadIdx.x;
    if (t == 0) {
        g_mm[0] = 0xFFFFFFFFu; g_mm[1] = 0u;
        g_mm[2] = 0xFFFFFFFFu; g_mm[3] = 0u;
        g_amax[0] = 0; g_amax[1] = 0; g_amax[2] = 0; g_amax[3] = 0;
    }
    if (t < COLS) g_sums[t] = 0;
}

// ---------------- maxabs reductions ----------------
__global__ void maxabs_x_kernel(const float* __restrict__ x, const float* __restrict__ nx) {
    const size_t N4 = (size_t)BSZ * IN_F / 4;
    float mx = 0.f, mn = 0.f;
    for (size_t i = (size_t)blockIdx.x * blockDim.x + threadIdx.x; i < N4;
         i += (size_t)gridDim.x * blockDim.x) {
        float4 vx = ((const float4*)x)[i];
        float4 vn = ((const float4*)nx)[i];
        mx = fmaxf(mx, fmaxf(fmaxf(fabsf(vx.x), fabsf(vx.y)), fmaxf(fabsf(vx.z), fabsf(vx.w))));
        mn = fmaxf(mn, fmaxf(fmaxf(fabsf(vn.x), fabsf(vn.y)), fmaxf(fabsf(vn.z), fabsf(vn.w))));
    }
    __shared__ float red[256];
    red[threadIdx.x] = mx; __syncthreads();
    for (int s = 128; s > 0; s >>= 1) {
        if (threadIdx.x < s) red[threadIdx.x] = fmaxf(red[threadIdx.x], red[threadIdx.x + s]);
        __syncthreads();
    }
    if (threadIdx.x == 0) atomicMax(&g_amax[0], __float_as_uint(red[0]));
    __syncthreads();
    red[threadIdx.x] = mn; __syncthreads();
    for (int s = 128; s > 0; s >>= 1) {
        if (threadIdx.x < s) red[threadIdx.x] = fmaxf(red[threadIdx.x], red[threadIdx.x + s]);
        __syncthreads();
    }
    if (threadIdx.x == 0) atomicMax(&g_amax[1], __float_as_uint(red[0]));
}
__global__ void maxabs_w_kernel(const float* __restrict__ w, const float* __restrict__ wn) {
    const size_t N4 = (size_t)OUT_F * IN_F / 4;
    float m2 = 0.f, m3 = 0.f;
    for (size_t i = (size_t)blockIdx.x * blockDim.x + threadIdx.x; i < N4;
         i += (size_t)gridDim.x * blockDim.x) {
        float4 vw = ((const float4*)w)[i];
        float4 vn = ((const float4*)wn)[i];
        m2 = fmaxf(m2, fmaxf(fmaxf(fabsf(vn.x), fabsf(vn.y)), fmaxf(fabsf(vn.z), fabsf(vn.w))));
        float p0 = __fadd_rn(vw.x, vn.x), p1 = __fadd_rn(vw.y, vn.y);
        float p2 = __fadd_rn(vw.z, vn.z), p3 = __fadd_rn(vw.w, vn.w);
        m3 = fmaxf(m3, fmaxf(fmaxf(fabsf(p0), fabsf(p1)), fmaxf(fabsf(p2), fabsf(p3))));
    }
    __shared__ float red[256];
    red[threadIdx.x] = m2; __syncthreads();
    for (int s = 128; s > 0; s >>= 1) {
        if (threadIdx.x < s) red[threadIdx.x] = fmaxf(red[threadIdx.x], red[threadIdx.x + s]);
        __syncthreads();
    }
    if (threadIdx.x == 0) atomicMax(&g_amax[2], __float_as_uint(red[0]));
    __syncthreads();
    red[threadIdx.x] = m3; __syncthreads();
    for (int s = 128; s > 0; s >>= 1) {
        if (threadIdx.x < s) red[threadIdx.x] = fmaxf(red[threadIdx.x], red[threadIdx.x + s]);
        __syncthreads();
    }
    if (threadIdx.x == 0) atomicMax(&g_amax[3], __float_as_uint(red[0]));
}

__global__ void scalesA_kernel() {
    if (threadIdx.x == 0) {
        for (int t = 0; t < 4; t++) {
            float am = __uint_as_float(g_amax[t]);
            float s1 = __fdiv_rn(am, 127.0f);
            float is1 = __fdiv_rn(127.0f, am);
            float s2 = __fdiv_rn(s1, 254.0f);      // full q2 range over residual +-s1/2
            float is2 = __fdiv_rn(1.0f, s2);
            g_cs[t * 4 + 0] = s1; g_cs[t * 4 + 1] = is1;
            g_cs[t * 4 + 2] = s2; g_cs[t * 4 + 3] = is2;
        }
    }
}

// ---------------- residual int8 quant helper ----------------
__device__ __forceinline__ void q2lvl(float v, float s1, float is1, float is2,
                                      int8_t& o1, int8_t& o2) {
    float q1 = rintf(__fmul_rn(v, is1));
    q1 = fminf(fmaxf(q1, -127.0f), 127.0f);
    float r = __fmaf_rn(-q1, s1, v);
    float q2 = rintf(__fmul_rn(r, is2));
    q2 = fminf(fmaxf(q2, -127.0f), 127.0f);
    o1 = (int8_t)(int)q1;
    o2 = (int8_t)(int)q2;
}

// ---------------- fused transpose+add + residual int8 quant ----------------
__global__ void prepsplit_x_kernel(const float* __restrict__ x, const float* __restrict__ nx) {
    __shared__ float tile[32][33];
    int c0 = blockIdx.x * 32, k0 = blockIdx.y * 32;
    int tx = threadIdx.x, ty = threadIdx.y;
    float s1x = g_cs[0], is1x = g_cs[1], is2x = g_cs[3];
    float s1n = g_cs[4], is1n = g_cs[5], is2n = g_cs[7];
#pragma unroll
    for (int i = ty; i < 32; i += 8) {
        size_t idx = (size_t)(c0 + i) * IN_F + k0 + tx;
        float vx = x[idx], vn = nx[idx];
        tile[i][tx] = __fadd_rn(vx, vn);
        int8_t a, b;
        q2lvl(vx, s1x, is1x, is2x, a, b);  g_q1x[idx]  = a; g_q2x[idx]  = b;
        q2lvl(vn, s1n, is1n, is2n, a, b);  g_q1nx[idx] = a; g_q2nx[idx] = b;
    }
    __syncthreads();
#pragma unroll
    for (int i = ty; i < 32; i += 8)
        g_a[(size_t)(k0 + i) * COLS + c0 + tx] = tile[tx][i];
}
__global__ void prepsplit_w_kernel(const float* __restrict__ w, const float* __restrict__ wn) {
    __shared__ float tile[32][33];
    int c0 = blockIdx.x * 32, k0 = blockIdx.y * 32;
    int tx = threadIdx.x, ty = threadIdx.y;
    float s1n = g_cs[8],  is1n = g_cs[9],  is2n = g_cs[11];
    float s1p = g_cs[12], is1p = g_cs[13], is2p = g_cs[15];
#pragma unroll
    for (int i = ty; i < 32; i += 8) {
        size_t idx = (size_t)(c0 + i) * IN_F + k0 + tx;
        float vw = w[idx], vn = wn[idx];
        float vp = __fadd_rn(vw, vn);
        tile[i][tx] = vp;
        int8_t a, b;
        q2lvl(vn, s1n, is1n, is2n, a, b);  g_q1wn[idx] = a; g_q2wn[idx] = b;
        q2lvl(vp, s1p, is1p, is2p, a, b);  g_q1wp[idx] = a; g_q2wp[idx] = b;
    }
    __syncthreads();
#pragma unroll
    for (int i = ty; i < 32; i += 8)
        g_a[(size_t)(k0 + i) * COLS + BSZ + c0 + tx] = tile[tx][i];
}

// ---------------- TWO fused permutation + 2x2-mix rounds (NO FMA) ----------------
__global__ void round2_kernel(int dir, int r,
                              const int* __restrict__ perm0,
                              const int* __restrict__ perm1,
                              const float* __restrict__ matsx0,
                              const float* __restrict__ matsx1,
                              int do_mm) {
    const float* in  = dir ? g_b : g_a;
    float*       out = dir ? g_a : g_b;
    int g   = blockIdx.y;
    int col = blockIdx.x * 256 + threadIdx.x;
    int i0 = __ldg(&perm1[2 * g]);
    int i1 = __ldg(&perm1[2 * g + 1]);
    int g0 = i0 >> 1, p0 = i0 & 1;
    int g1 = i1 >> 1, p1 = i1 & 1;
    int ra0 = __ldg(&perm0[2 * g0]), rb0 = __ldg(&perm0[2 * g0 + 1]);
    int ra1 = __ldg(&perm0[2 * g1]), rb1 = __ldg(&perm0[2 * g1 + 1]);
    bool isx = (col < BSZ / 4);
    const float* m0base = isx ? matsx0 : (g_wmats + (size_t)r * GROUPS * 4);
    const float* m1base = isx ? matsx1 : (g_wmats + (size_t)(r + 1) * GROUPS * 4);
    float4 mA = __ldg((const float4*)(m0base + (size_t)g0 * 4));
    float4 mB = __ldg((const float4*)(m0base + (size_t)g1 * 4));
    float4 mC = __ldg((const float4*)(m1base + (size_t)g * 4));
    float c00 = p0 ? mA.z : mA.x, c01 = p0 ? mA.w : mA.y;
    float c10 = p1 ? mB.z : mB.x, c11 = p1 ? mB.w : mB.y;
    float4 a0 = ((const float4*)(in + (size_t)ra0 * COLS))[col];
    float4 b0 = ((const float4*)(in + (size_t)rb0 * COLS))[col];
    float4 a1 = ((const float4*)(in + (size_t)ra1 * COLS))[col];
    float4 b1 = ((const float4*)(in + (size_t)rb1 * COLS))[col];
    float4 v0, v1, o0, o1;
    v0.x = __fadd_rn(__fmul_rn(c00, a0.x), __fmul_rn(c01, b0.x));
    v0.y = __fadd_rn(__fmul_rn(c00, a0.y), __fmul_rn(c01, b0.y));
    v0.z = __fadd_rn(__fmul_rn(c00, a0.z), __fmul_rn(c01, b0.z));
    v0.w = __fadd_rn(__fmul_rn(c00, a0.w), __fmul_rn(c01, b0.w));
    v1.x = __fadd_rn(__fmul_rn(c10, a1.x), __fmul_rn(c11, b1.x));
    v1.y = __fadd_rn(__fmul_rn(c10, a1.y), __fmul_rn(c11, b1.y));
    v1.z = __fadd_rn(__fmul_rn(c10, a1.z), __fmul_rn(c11, b1.z));
    v1.w = __fadd_rn(__fmul_rn(c10, a1.w), __fmul_rn(c11, b1.w));
    o0.x = __fadd_rn(__fmul_rn(mC.x, v0.x), __fmul_rn(mC.y, v1.x));
    o0.y = __fadd_rn(__fmul_rn(mC.x, v0.y), __fmul_rn(mC.y, v1.y));
    o0.z = __fadd_rn(__fmul_rn(mC.x, v0.z), __fmul_rn(mC.y, v1.z));
    o0.w = __fadd_rn(__fmul_rn(mC.x, v0.w), __fmul_rn(mC.y, v1.w));
    o1.x = __fadd_rn(__fmul_rn(mC.z, v0.x), __fmul_rn(mC.w, v1.x));
    o1.y = __fadd_rn(__fmul_rn(mC.z, v0.y), __fmul_rn(mC.w, v1.y));
    o1.z = __fadd_rn(__fmul_rn(mC.z, v0.z), __fmul_rn(mC.w, v1.z));
    o1.w = __fadd_rn(__fmul_rn(mC.z, v0.w), __fmul_rn(mC.w, v1.w));
    ((float4*)(out + (size_t)(2 * g)     * COLS))[col] = o0;
    ((float4*)(out + (size_t)(2 * g + 1) * COLS))[col] = o1;

    if (do_mm) {
        float lo = fminf(fminf(fminf(o0.x, o0.y), fminf(o0.z, o0.w)),
                         fminf(fminf(o1.x, o1.y), fminf(o1.z, o1.w)));
        float hi = fmaxf(fmaxf(fmaxf(o0.x, o0.y), fmaxf(o0.z, o0.w)),
                         fmaxf(fmaxf(o1.x, o1.y), fmaxf(o1.z, o1.w)));
        __shared__ float red[256];
        red[threadIdx.x] = lo; __syncthreads();
        for (int s = 128; s > 0; s >>= 1) {
            if (threadIdx.x < s) red[threadIdx.x] = fminf(red[threadIdx.x], red[threadIdx.x + s]);
            __syncthreads();
        }
        if (threadIdx.x == 0) atomicMin(&g_mm[isx ? 0 : 2], enc_f(red[0]));
        __syncthreads();
        red[threadIdx.x] = hi; __syncthreads();
        for (int s = 128; s > 0; s >>= 1) {
            if (threadIdx.x < s) red[threadIdx.x] = fmaxf(red[threadIdx.x], red[threadIdx.x + s]);
            __syncthreads();
        }
        if (threadIdx.x == 0) atomicMax(&g_mm[isx ? 1 : 3], enc_f(red[0]));
    }
}

// ---------------- qparams + segment scales ----------------
__global__ void qparams_kernel() {
    if (threadIdx.x == 0) {
        float lx = dec_f(g_mm[0]), hx = dec_f(g_mm[1]);
        float sx = __fdiv_rn(__fsub_rn(hx, lx), 255.0f);
        float zx = rintf(__fsub_rn(-128.0f, __fdiv_rn(lx, sx)));
        float lw = dec_f(g_mm[2]), hw = dec_f(g_mm[3]);
        float sw = __fdiv_rn(__fsub_rn(hw, lw), 255.0f);
        float zw = rintf(__fsub_rn(-128.0f, __fdiv_rn(lw, sw)));
        g_qp[0] = sx; g_qp[1] = zx; g_qp[2] = sw; g_qp[3] = zw;
        float s1x = g_cs[0],  s2x = g_cs[2];
        float s1n = g_cs[4],  s2n = g_cs[6];
        float s1wn = g_cs[8],  s2wn = g_cs[10];
        float s1wp = g_cs[12], s2wp = g_cs[14];
        g_segscale[0] = __fmul_rn(sx, sw);
        g_segscale[1] = -__fmul_rn(s1x, s1wn);
        g_segscale[2] = -__fmul_rn(s1x, s2wn);
        g_segscale[3] = -__fmul_rn(s2x, s1wn);
        g_segscale[4] = -__fmul_rn(s2x, s2wn);
        g_segscale[5] = -__fmul_rn(s1n, s1wp);
        g_segscale[6] = -__fmul_rn(s1n, s2wp);
        g_segscale[7] = -__fmul_rn(s2n, s1wp);
        g_segscale[8] = -__fmul_rn(s2n, s2wp);
    }
}

// ---------------- quantize -> int8 q, transposed to K-major + row sums ----------------
__global__ void quantT_kernel() {
    __shared__ float tile[32][33];
    int c0 = blockIdx.x * 32, k0 = blockIdx.y * 32;
    int tx = threadIdx.x, ty = threadIdx.y;
    bool isx = (c0 < BSZ);
    float s = isx ? g_qp[0] : g_qp[2];
    float z = isx ? g_qp[1] : g_qp[3];
#pragma unroll
    for (int i = ty; i < 32; i += 8) {
        float t = g_a[(size_t)(k0 + i) * COLS + c0 + tx];
        float q = rintf(__fadd_rn(__fdiv_rn(t, s), z));
        q = fminf(fmaxf(q, -128.0f), 127.0f);
        tile[i][tx] = q;
    }
    __syncthreads();
    int8_t* dst = isx ? g_qx8 : g_qw8;
    int cb = isx ? c0 : (c0 - BSZ);
#pragma unroll
    for (int i = ty; i < 32; i += 8) {
        int qi = (int)tile[tx][i];
        dst[(size_t)(cb + i) * IN_F + k0 + tx] = (int8_t)qi;
        int wsum = __reduce_add_sync(0xFFFFFFFFu, qi);
        if (tx == 0) atomicAdd(&g_sums[c0 + i], wsum);
    }
}

// ---------------- int8 TMA-fed mma.sync GEMM, 9 segments ----------------
// seg0:(qx,qw)+sxsw ; 1:(q1x,q1wn) 2:(q1x,q2wn) 3:(q2x,q1wn) 4:(q2x,q2wn)  (-scale)
// 5:(q1nx,q1wp) 6:(q1nx,q2wp) 7:(q2nx,q1wp) 8:(q2nx,q2wp)                  (-scale)
// epilogue: out = accf + sxsw*(-zx*Sw - zw*Sx + K*zx*zw) + bias
__global__ void __launch_bounds__(256, 2)
gemm_s8_kernel(const __grid_constant__ TmapPack tp,
               const float* __restrict__ bias, float* __restrict__ out) {
    extern __shared__ __align__(1024) char smem[];
    uint32_t sb = smem_u32(smem);
    const int tid = threadIdx.x, lane = tid & 31, warp = tid >> 5;
    const int bn = blockIdx.x, bm = blockIdx.y;
    const int wm = (warp >> 1) * 32;
    const int wn = (warp & 1) * 32;

    if (tid == 0) {
#pragma unroll
        for (int i = 0; i < NSTG; i++) MBAR_INIT(sb + i * 8, 1);
    }
    __syncthreads();

    int   acc_s[2][4][4];
    float acc_f[2][4][4];
#pragma unroll
    for (int a = 0; a < 2; a++)
#pragma unroll
        for (int b = 0; b < 4; b++)
#pragma unroll
            for (int q = 0; q < 4; q++) { acc_s[a][b][q] = 0; acc_f[a][b][q] = 0.f; }

    float sc[NSEG];
#pragma unroll
    for (int i = 0; i < NSEG; i++) sc[i] = g_segscale[i];

    static const int asel[NSEG] = {0, 1, 1, 2, 2, 3, 3, 4, 4};
    static const int bsel[NSEG] = {0, 1, 2, 1, 2, 3, 4, 3, 4};

    if (tid == 0) {
#pragma unroll
        for (int p = 0; p < NSTG; p++) {
            int kx = p * KCH;   // p < 4 -> seg 0
            uint32_t st = sb + 1024 + p * ST_BYTES;
            MBAR_EXPECT_TX(sb + p * 8, ST_BYTES);
            TMA_2D(st,           &tp.a[0], kx, bm * 128, sb + p * 8);
            TMA_2D(st + A_BYTES, &tp.b[0], kx, bn * 64,  sb + p * 8);
        }
    }

    for (int c = 0; c < NCH; c++) {
        int s = c & (NSTG - 1), ph = (c / NSTG) & 1;
        MBAR_WAIT(sb + s * 8, ph);
        uint32_t abase = sb + 1024 + s * ST_BYTES;
        uint32_t bbase = abase + A_BYTES;
#pragma unroll
        for (int kq = 0; kq < 4; kq++) {
            uint32_t af[2][4], bf[4][2];
#pragma unroll
            for (int mt = 0; mt < 2; mt++) {
                int row = wm + mt * 16 + (lane & 15);
                int chk = kq * 2 + (lane >> 4);
                uint32_t off = (uint32_t)(row * 128 + chk * 16);
                uint32_t ad = abase + (off ^ ((off >> 3) & 0x70));
                asm volatile("ldmatrix.sync.aligned.m8n8.x4.shared.b16 {%0,%1,%2,%3},[%4];"
                             : "=r"(af[mt][0]), "=r"(af[mt][1]), "=r"(af[mt][2]), "=r"(af[mt][3])
                             : "r"(ad));
            }
#pragma unroll
            for (int nt = 0; nt < 4; nt++) {
                int row = wn + nt * 8 + (lane & 7);
                int chk = kq * 2 + ((lane >> 3) & 1);
                uint32_t off = (uint32_t)(row * 128 + chk * 16);
                uint32_t bd = bbase + (off ^ ((off >> 3) & 0x70));
                asm volatile("ldmatrix.sync.aligned.m8n8.x2.shared.b16 {%0,%1},[%2];"
                             : "=r"(bf[nt][0]), "=r"(bf[nt][1]) : "r"(bd));
            }
#pragma unroll
            for (int mt = 0; mt < 2; mt++)
#pragma unroll
                for (int nt = 0; nt < 4; nt++) {
                    asm volatile(
                        "mma.sync.aligned.m16n8k32.row.col.s32.s8.s8.s32 "
                        "{%0,%1,%2,%3},{%4,%5,%6,%7},{%8,%9},{%0,%1,%2,%3};"
                        : "+r"(acc_s[mt][nt][0]), "+r"(acc_s[mt][nt][1]),
                          "+r"(acc_s[mt][nt][2]), "+r"(acc_s[mt][nt][3])
                        : "r"(af[mt][0]), "r"(af[mt][1]), "r"(af[mt][2]), "r"(af[mt][3]),
                          "r"(bf[nt][0]), "r"(bf[nt][1]));
                }
        }
        if ((c & (CHPS - 1)) == CHPS - 1) {   // segment boundary: fold scale
            float f = sc[c >> 5];
#pragma unroll
            for (int a = 0; a < 2; a++)
#pragma unroll
                for (int b = 0; b < 4; b++)
#pragma unroll
                    for (int q = 0; q < 4; q++) {
                        acc_f[a][b][q] = __fmaf_rn(f, __int2float_rn(acc_s[a][b][q]), acc_f[a][b][q]);
                        acc_s[a][b][q] = 0;
                    }
        }
        __syncthreads();
        if (tid == 0 && c + NSTG < NCH) {
            int nc = c + NSTG;
            int seg = nc >> 5, kx = (nc & (CHPS - 1)) * KCH;
            uint32_t st = sb + 1024 + s * ST_BYTES;
            MBAR_EXPECT_TX(sb + s * 8, ST_BYTES);
            TMA_2D(st,           &tp.a[asel[seg]], kx, bm * 128, sb + s * 8);
            TMA_2D(st + A_BYTES, &tp.b[bsel[seg]], kx, bn * 64,  sb + s * 8);
        }
    }

    // epilogue
    const float sxsw = __fmul_rn(g_qp[0], g_qp[2]);
    const float zx = g_qp[1], zw = g_qp[3];
    const float kzz = __fmul_rn(4096.0f, __fmul_rn(zx, zw));
    const int grp = lane >> 2, tig = lane & 3;
#pragma unroll
    for (int mt = 0; mt < 2; mt++)
#pragma unroll
        for (int nt = 0; nt < 4; nt++) {
            int gm = bm * 128 + wm + mt * 16 + grp;
            int gn = bn * 64 + wn + nt * 8 + tig * 2;
            float Sx0 = (float)g_sums[gm], Sx1 = (float)g_sums[gm + 8];
            float Sw0 = (float)g_sums[BSZ + gn], Sw1 = (float)g_sums[BSZ + gn + 1];
            float b0 = bias[gn], b1 = bias[gn + 1];
            float R00 = __fmul_rn(sxsw, __fmaf_rn(-zx, Sw0, __fmaf_rn(-zw, Sx0, kzz)));
            float R01 = __fmul_rn(sxsw, __fmaf_rn(-zx, Sw1, __fmaf_rn(-zw, Sx0, kzz)));
            float R10 = __fmul_rn(sxsw, __fmaf_rn(-zx, Sw0, __fmaf_rn(-zw, Sx1, kzz)));
            float R11 = __fmul_rn(sxsw, __fmaf_rn(-zx, Sw1, __fmaf_rn(-zw, Sx1, kzz)));
            float2 v0, v1;
            v0.x = __fadd_rn(__fadd_rn(acc_f[mt][nt][0], R00), b0);
            v0.y = __fadd_rn(__fadd_rn(acc_f[mt][nt][1], R01), b1);
            v1.x = __fadd_rn(__fadd_rn(acc_f[mt][nt][2], R10), b0);
            v1.y = __fadd_rn(__fadd_rn(acc_f[mt][nt][3], R11), b1);
            *(float2*)&out[(size_t)gm * OUT_F + gn]       = v0;
            *(float2*)&out[(size_t)(gm + 8) * OUT_F + gn] = v1;
        }
}

// ---------------- host ----------------
typedef CUresult (*EncodeFn)(CUtensorMap*, CUtensorMapDataType, cuuint32_t, void*,
                             const cuuint64_t*, const cuuint64_t*, const cuuint32_t*,
                             const cuuint32_t*, CUtensorMapInterleave, CUtensorMapSwizzle,
                             CUtensorMapL2promotion, CUtensorMapFloatOOBfill);

static void encode_map(EncodeFn enc, CUtensorMap* m, void* ptr, int rows, int boxrows) {
    cuuint64_t dims[2]    = {(cuuint64_t)IN_F, (cuuint64_t)rows};
    cuuint64_t strides[1] = {(cuuint64_t)IN_F};
    cuuint32_t box[2]     = {(cuuint32_t)KCH, (cuuint32_t)boxrows};
    cuuint32_t estr[2]    = {1, 1};
    enc(m, CU_TENSOR_MAP_DATA_TYPE_UINT8, 2, ptr, dims, strides, box, estr,
        CU_TENSOR_MAP_INTERLEAVE_NONE, CU_TENSOR_MAP_SWIZZLE_128B,
        CU_TENSOR_MAP_L2_PROMOTION_L2_128B, CU_TENSOR_MAP_FLOAT_OOB_FILL_NONE);
}

extern "C" void kernel_launch(void* const* d_in, const int* in_sizes, int n_in,
                              void* d_out, int out_size) {
    const float* x    = (const float*)d_in[0];
    const float* wgt  = (const float*)d_in[1];
    const float* bias = (const float*)d_in[2];
    const float* wn   = (const float*)d_in[3];
    const float* nx   = (const float*)d_in[4];
    const int*   perms= (const int*)  d_in[5];
    const float* mats = (const float*)d_in[6];
    float* out = (float*)d_out;

    make_wmats_kernel<<<(ROUNDS * GROUPS + 255) / 256, 256>>>(mats);
    reset_kernel<<<(COLS + 255) / 256, 256>>>();
    maxabs_x_kernel<<<1024, 256>>>(x, nx);
    maxabs_w_kernel<<<256, 256>>>(wgt, wn);
    scalesA_kernel<<<1, 32>>>();

    prepsplit_x_kernel<<<dim3(BSZ / 32, IN_F / 32), dim3(32, 8)>>>(x, nx);
    prepsplit_w_kernel<<<dim3(OUT_F / 32, IN_F / 32), dim3(32, 8)>>>(wgt, wn);

    for (int p = 0; p < ROUNDS / 2; p++) {
        int r = 2 * p;
        round2_kernel<<<dim3(COLS4 / 256, GROUPS), 256>>>(
            p & 1, r,
            perms + (size_t)r * IN_F, perms + (size_t)(r + 1) * IN_F,
            mats + (size_t)r * GROUPS * 4, mats + (size_t)(r + 1) * GROUPS * 4,
            (p == ROUNDS / 2 - 1) ? 1 : 0);
    }

    qparams_kernel<<<1, 32>>>();
    quantT_kernel<<<dim3(COLS / 32, IN_F / 32), dim3(32, 8)>>>();

    void* fp = nullptr;
#if CUDART_VERSION >= 12050
    cudaDriverEntryPointQueryResult qr;
    cudaGetDriverEntryPointByVersion("cuTensorMapEncodeTiled", &fp, 12000,
                                     cudaEnableDefault, &qr);
#else
    cudaGetDriverEntryPoint("cuTensorMapEncodeTiled", &fp, cudaEnableDefault);
#endif
    EncodeFn enc = (EncodeFn)fp;

    void *pa0, *pa1, *pa2, *pa3, *pa4, *pb0, *pb1, *pb2, *pb3, *pb4;
    cudaGetSymbolAddress(&pa0, g_qx8);  cudaGetSymbolAddress(&pa1, g_q1x);
    cudaGetSymbolAddress(&pa2, g_q2x);  cudaGetSymbolAddress(&pa3, g_q1nx);
    cudaGetSymbolAddress(&pa4, g_q2nx); cudaGetSymbolAddress(&pb0, g_qw8);
    cudaGetSymbolAddress(&pb1, g_q1wn); cudaGetSymbolAddress(&pb2, g_q2wn);
    cudaGetSymbolAddress(&pb3, g_q1wp); cudaGetSymbolAddress(&pb4, g_q2wp);

    TmapPack tp;
    encode_map(enc, &tp.a[0], pa0, BSZ,   128);
    encode_map(enc, &tp.a[1], pa1, BSZ,   128);
    encode_map(enc, &tp.a[2], pa2, BSZ,   128);
    encode_map(enc, &tp.a[3], pa3, BSZ,   128);
    encode_map(enc, &tp.a[4], pa4, BSZ,   128);
    encode_map(enc, &tp.b[0], pb0, OUT_F, 64);
    encode_map(enc, &tp.b[1], pb1, OUT_F, 64);
    encode_map(enc, &tp.b[2], pb2, OUT_F, 64);
    encode_map(enc, &tp.b[3], pb3, OUT_F, 64);
    encode_map(enc, &tp.b[4], pb4, OUT_F, 64);

    cudaFuncSetAttribute(gemm_s8_kernel, cudaFuncAttributeMaxDynamicSharedMemorySize, DSMEM);
    gemm_s8_kernel<<<dim3(OUT_F / 64, BSZ / 128), 256, DSMEM>>>(tp, bias, out);
}